// round 1
// baseline (speedup 1.0000x reference)
#include <cuda_runtime.h>
#include <cstdint>

// Problem constants
#define B 32
#define HW 512
#define NPIX (HW * HW)          // 262144 per map
#define NPATCH 4
#define C 3
#define P 128                   // PATCH_SIZE == eps
#define HALF 64
#define MARGIN 32
#define PATCH_OUT_ELEMS (B * NPATCH * C * P * P)   // 6291456

// Scratch (no allocations allowed)
__device__ unsigned long long g_best[B];
__device__ int g_boxes[B * NPATCH * 4];   // [b][k][{x1,y1,x2,y2}]

// ---------------------------------------------------------------------------
// init: reset accumulators
// ---------------------------------------------------------------------------
__global__ void k_init() {
    if (threadIdx.x < B) g_best[threadIdx.x] = 0ULL;
}

// ---------------------------------------------------------------------------
// argmax pass k: masked argmax per batch, mask = union of k previous boxes
// expanded by MARGIN. Packs (orderable float bits << 32) | ~idx so that
// atomicMax == (max value, first-occurrence index).
// ---------------------------------------------------------------------------
__global__ __launch_bounds__(256)
void k_argmax(const float* __restrict__ umap, int k) {
    const int b = blockIdx.y;
    const float4* __restrict__ u = (const float4*)(umap + (size_t)b * NPIX);

    __shared__ int sb[NPATCH - 1][4];
    if (threadIdx.x < k * 4)
        sb[threadIdx.x >> 2][threadIdx.x & 3] = g_boxes[b * 16 + threadIdx.x];
    __syncthreads();

    unsigned long long best = 0ULL;
    const int stride = blockDim.x * gridDim.x;
    for (int v = blockIdx.x * blockDim.x + threadIdx.x; v < NPIX / 4; v += stride) {
        float4 f = u[v];
        int base = v * 4;
        int y = base >> 9;
        int x0 = base & (HW - 1);
        float vals[4] = {f.x, f.y, f.z, f.w};
#pragma unroll
        for (int e = 0; e < 4; e++) {
            int x = x0 + e;
            bool sup = false;
            for (int j = 0; j < k; j++) {
                sup |= (y >= sb[j][1] - MARGIN) & (y < sb[j][3] + MARGIN) &
                       (x >= sb[j][0] - MARGIN) & (x < sb[j][2] + MARGIN);
            }
            if (!sup) {
                unsigned ub = __float_as_uint(vals[e]);
                ub = (ub & 0x80000000u) ? ~ub : (ub | 0x80000000u);
                unsigned long long p =
                    ((unsigned long long)ub << 32) | (unsigned)(~(unsigned)(base + e));
                best = (p > best) ? p : best;
            }
        }
    }

    // warp reduce
#pragma unroll
    for (int off = 16; off > 0; off >>= 1) {
        unsigned long long o = __shfl_down_sync(0xFFFFFFFFu, best, off);
        best = (o > best) ? o : best;
    }
    __shared__ unsigned long long sred[8];
    const int lane = threadIdx.x & 31, wid = threadIdx.x >> 5;
    if (lane == 0) sred[wid] = best;
    __syncthreads();
    if (wid == 0) {
        best = (lane < (blockDim.x >> 5)) ? sred[lane] : 0ULL;
#pragma unroll
        for (int off = 4; off > 0; off >>= 1) {
            unsigned long long o = __shfl_down_sync(0xFFFFFFFFu, best, off);
            best = (o > best) ? o : best;
        }
        if (lane == 0) atomicMax(&g_best[b], best);
    }
}

// ---------------------------------------------------------------------------
// coords pass k: decode winner, apply border fix, store box, emit float
// coords, reset accumulator for next pass.
// ---------------------------------------------------------------------------
__global__ void k_coords(float* __restrict__ out_coords, int k) {
    int b = threadIdx.x;
    if (b >= B) return;
    unsigned long long p = g_best[b];
    int idx = (int)(~(unsigned)(p & 0xFFFFFFFFu));
    int yc = idx >> 9;
    int xc = idx & (HW - 1);

    int x1 = max(0, xc - HALF), x2 = min(HW, xc + HALF);
    if (x2 - x1 < P) { if (x1 == 0) x2 = P; else x1 = x2 - P; }
    int y1 = max(0, yc - HALF), y2 = min(HW, yc + HALF);
    if (y2 - y1 < P) { if (y1 == 0) y2 = P; else y1 = y2 - P; }

    int* bx = &g_boxes[(b * NPATCH + k) * 4];
    bx[0] = x1; bx[1] = y1; bx[2] = x2; bx[3] = y2;

    float* oc = out_coords + (b * NPATCH + k) * 4;
    oc[0] = (float)x1; oc[1] = (float)y1; oc[2] = (float)x2; oc[3] = (float)y2;

    g_best[b] = 0ULL;   // ready for next pass
}

// ---------------------------------------------------------------------------
// extract: one block per (b, n, c); copy 128x128 window, float4 stores
// ---------------------------------------------------------------------------
__global__ __launch_bounds__(256)
void k_extract(const float* __restrict__ images, float* __restrict__ out) {
    const int blk = blockIdx.x;
    const int c = blk % C;
    const int n = (blk / C) % NPATCH;
    const int b = blk / (C * NPATCH);

    const int x1 = g_boxes[(b * NPATCH + n) * 4 + 0];
    const int y1 = g_boxes[(b * NPATCH + n) * 4 + 1];

    const float* __restrict__ src =
        images + (((size_t)(b * C + c) * HW) + y1) * HW + x1;
    float4* __restrict__ dst =
        (float4*)(out + (size_t)((b * NPATCH + n) * C + c) * (P * P));

    // P*P/4 = 4096 float4 per (b,n,c); 32 float4 per row
    for (int v = threadIdx.x; v < (P * P) / 4; v += blockDim.x) {
        const int i = v >> 5;
        const int j = (v & 31) * 4;
        const float* s = src + (size_t)i * HW + j;
        dst[v] = make_float4(s[0], s[1], s[2], s[3]);
    }
}

// ---------------------------------------------------------------------------
extern "C" void kernel_launch(void* const* d_in, const int* in_sizes, int n_in,
                              void* d_out, int out_size) {
    const float* images = (const float*)d_in[0];           // [32,3,512,512]
    const float* umaps  = (const float*)d_in[1];            // [32,1,512,512]
    float* out = (float*)d_out;
    float* out_coords = out + PATCH_OUT_ELEMS;

    k_init<<<1, 32>>>();

    dim3 agrid(32, B);
    for (int k = 0; k < NPATCH; k++) {
        k_argmax<<<agrid, 256>>>(umaps, k);
        k_coords<<<1, 32>>>(out_coords, k);
    }

    k_extract<<<B * NPATCH * C, 256>>>(images, out);
}

// round 3
// speedup vs baseline: 1.1949x; 1.1949x over previous
#include <cuda_runtime.h>
#include <cstdint>

#define B 32
#define HW 512
#define NPIX (HW * HW)
#define NPATCH 4
#define C 3
#define P 128
#define HALF 64
#define MARGIN 32
#define TILE 32
#define TPD (HW / TILE)          // 16 tiles per dim
#define NTILE (TPD * TPD)        // 256 tiles per map
#define PATCH_OUT_ELEMS (B * NPATCH * C * P * P)

// Scratch (device globals; fully overwritten each call -> deterministic)
__device__ unsigned long long g_tiles[B * NTILE];
__device__ int g_boxes[B * NPATCH * 4];

__device__ __forceinline__ unsigned flipf(float v) {
    unsigned ub = __float_as_uint(v);
    return (ub & 0x80000000u) ? ~ub : (ub | 0x80000000u);
}

// ---------------------------------------------------------------------------
// Pass A: per-tile packed argmax (value||~idx), no suppression. Memory-bound.
// grid (NTILE, B), 256 threads; each thread owns one float4 of its tile.
// ---------------------------------------------------------------------------
__global__ __launch_bounds__(256)
void k_tilemax(const float* __restrict__ umap) {
    const int b = blockIdx.y;
    const int tile = blockIdx.x;
    const int tx1 = (tile & (TPD - 1)) * TILE;
    const int ty1 = (tile >> 4) * TILE;

    const int t = threadIdx.x;
    const int y = ty1 + (t >> 3);
    const int x = tx1 + ((t & 7) << 2);

    const float4 f = *(const float4*)(umap + ((size_t)b << 18) + (y << 9) + x);

    // max of 4 with first-occurrence element
    float m = f.x; int e = 0;
    if (f.y > m) { m = f.y; e = 1; }
    if (f.z > m) { m = f.z; e = 2; }
    if (f.w > m) { m = f.w; e = 3; }

    unsigned long long best =
        ((unsigned long long)flipf(m) << 32) | (unsigned)~(unsigned)((y << 9) + x + e);

#pragma unroll
    for (int off = 16; off > 0; off >>= 1) {
        unsigned long long o = __shfl_down_sync(0xFFFFFFFFu, best, off);
        best = (o > best) ? o : best;
    }
    __shared__ unsigned long long sred[8];
    const int lane = t & 31, wid = t >> 5;
    if (lane == 0) sred[wid] = best;
    __syncthreads();
    if (wid == 0) {
        best = (lane < 8) ? sred[lane] : 0ULL;
#pragma unroll
        for (int off = 4; off > 0; off >>= 1) {
            unsigned long long o = __shfl_down_sync(0xFFFFFFFFu, best, off);
            best = (o > best) ? o : best;
        }
        if (lane == 0) g_tiles[b * NTILE + tile] = best;
    }
}

// ---------------------------------------------------------------------------
// Pass B: all 4 greedy selections fused. One block (256 thr) per batch.
// Incremental tile invalidation + warp-per-tile rescan of boundary tiles.
// ---------------------------------------------------------------------------
__global__ __launch_bounds__(256)
void k_select(const float* __restrict__ umap, float* __restrict__ out_coords) {
    const int b = blockIdx.x;
    const int t = threadIdx.x;
    const int lane = t & 31, wid = t >> 5;
    const float* __restrict__ um = umap + ((size_t)b << 18);

    __shared__ unsigned long long stile[NTILE];
    __shared__ unsigned long long sred[8];
    __shared__ int sboxes[NPATCH][4];
    __shared__ int slist[64];
    __shared__ int scount;

    stile[t] = g_tiles[b * NTILE + t];

    for (int k = 0; k < NPATCH; k++) {
        __syncthreads();
        // -- block-wide max over 256 tile entries --
        unsigned long long v = stile[t];
#pragma unroll
        for (int off = 16; off > 0; off >>= 1) {
            unsigned long long o = __shfl_down_sync(0xFFFFFFFFu, v, off);
            v = (o > v) ? o : v;
        }
        if (lane == 0) sred[wid] = v;
        __syncthreads();
        if (t == 0) {
            unsigned long long w = sred[0];
#pragma unroll
            for (int j = 1; j < 8; j++) w = (sred[j] > w) ? sred[j] : w;
            const int idx = (int)(~(unsigned)(w & 0xFFFFFFFFu));
            const int yc = idx >> 9, xc = idx & (HW - 1);

            int x1 = max(0, xc - HALF), x2 = min(HW, xc + HALF);
            if (x2 - x1 < P) { if (x1 == 0) x2 = P; else x1 = x2 - P; }
            int y1 = max(0, yc - HALF), y2 = min(HW, yc + HALF);
            if (y2 - y1 < P) { if (y1 == 0) y2 = P; else y1 = y2 - P; }

            sboxes[k][0] = x1; sboxes[k][1] = y1;
            sboxes[k][2] = x2; sboxes[k][3] = y2;

            int* bx = &g_boxes[(b * NPATCH + k) * 4];
            bx[0] = x1; bx[1] = y1; bx[2] = x2; bx[3] = y2;
            float* oc = out_coords + (b * NPATCH + k) * 4;
            oc[0] = (float)x1; oc[1] = (float)y1;
            oc[2] = (float)x2; oc[3] = (float)y2;
            scount = 0;
        }
        __syncthreads();
        if (k == NPATCH - 1) break;

        // -- classify each tile against the newly added expanded box --
        const int ex1 = sboxes[k][0] - MARGIN, ey1 = sboxes[k][1] - MARGIN;
        const int ex2 = sboxes[k][2] + MARGIN, ey2 = sboxes[k][3] + MARGIN;
        {
            const int tx1 = (t & (TPD - 1)) * TILE, ty1 = (t >> 4) * TILE;
            const int tx2 = tx1 + TILE, ty2 = ty1 + TILE;
            const bool inter = (tx1 < ex2) && (tx2 > ex1) && (ty1 < ey2) && (ty2 > ey1);
            if (inter) {
                const bool full = (tx1 >= ex1) && (tx2 <= ex2) && (ty1 >= ey1) && (ty2 <= ey2);
                if (full) stile[t] = 0ULL;
                else slist[atomicAdd(&scount, 1)] = t;
            }
        }
        __syncthreads();

        // -- warp-per-tile rescan of partially-covered tiles (check boxes 0..k) --
        const int cnt = scount;
        for (int li = wid; li < cnt; li += 8) {
            const int tile = slist[li];
            const int tx1 = (tile & (TPD - 1)) * TILE;
            const int ty1 = (tile >> 4) * TILE;
            unsigned long long best = 0ULL;
#pragma unroll
            for (int q = 0; q < 8; q++) {
                const int f4 = q * 32 + lane;             // 256 float4 per tile
                const int y = ty1 + (f4 >> 3);
                const int xb = tx1 + ((f4 & 7) << 2);
                const float4 f = *(const float4*)(um + (y << 9) + xb);
                const float vals[4] = {f.x, f.y, f.z, f.w};
#pragma unroll
                for (int e = 0; e < 4; e++) {
                    const int x = xb + e;
                    bool sup = false;
                    for (int j = 0; j <= k; j++)
                        sup |= (y >= sboxes[j][1] - MARGIN) & (y < sboxes[j][3] + MARGIN) &
                               (x >= sboxes[j][0] - MARGIN) & (x < sboxes[j][2] + MARGIN);
                    if (!sup) {
                        unsigned long long pk =
                            ((unsigned long long)flipf(vals[e]) << 32) |
                            (unsigned)~(unsigned)((y << 9) + x);
                        best = (pk > best) ? pk : best;
                    }
                }
            }
#pragma unroll
            for (int off = 16; off > 0; off >>= 1) {
                unsigned long long o = __shfl_down_sync(0xFFFFFFFFu, best, off);
                best = (o > best) ? o : best;
            }
            if (lane == 0) stile[tile] = best;
        }
    }
}

// ---------------------------------------------------------------------------
// Pass C: extract — one block per (b, n, c); 128x128 window copy
// ---------------------------------------------------------------------------
__global__ __launch_bounds__(256)
void k_extract(const float* __restrict__ images, float* __restrict__ out) {
    const int blk = blockIdx.x;
    const int c = blk % C;
    const int n = (blk / C) % NPATCH;
    const int b = blk / (C * NPATCH);

    const int x1 = g_boxes[(b * NPATCH + n) * 4 + 0];
    const int y1 = g_boxes[(b * NPATCH + n) * 4 + 1];

    const float* __restrict__ src =
        images + (((size_t)(b * C + c) * HW) + y1) * HW + x1;
    float4* __restrict__ dst =
        (float4*)(out + (size_t)((b * NPATCH + n) * C + c) * (P * P));

    for (int v = threadIdx.x; v < (P * P) / 4; v += blockDim.x) {
        const int i = v >> 5;
        const int j = (v & 31) * 4;
        const float* s = src + (size_t)i * HW + j;
        dst[v] = make_float4(s[0], s[1], s[2], s[3]);
    }
}

// ---------------------------------------------------------------------------
extern "C" void kernel_launch(void* const* d_in, const int* in_sizes, int n_in,
                              void* d_out, int out_size) {
    const float* images = (const float*)d_in[0];   // [32,3,512,512]
    const float* umaps  = (const float*)d_in[1];   // [32,1,512,512]
    float* out = (float*)d_out;
    float* out_coords = out + PATCH_OUT_ELEMS;

    k_tilemax<<<dim3(NTILE, B), 256>>>(umaps);
    k_select<<<B, 256>>>(umaps, out_coords);
    k_extract<<<B * NPATCH * C, 256>>>(images, out);
}

// round 4
// speedup vs baseline: 2.7508x; 2.3021x over previous
#include <cuda_runtime.h>
#include <cstdint>

#define B 32
#define HW 512
#define NPIX (HW * HW)
#define NPATCH 4
#define C 3
#define P 128
#define HALF 64
#define MARGIN 32
#define TILE 32
#define TPD (HW / TILE)          // 16
#define NTILE (TPD * TPD)        // 256
#define PATCH_OUT_ELEMS (B * NPATCH * C * P * P)

__device__ unsigned long long g_tiles[B * NTILE];
__device__ int g_boxes[B * NPATCH * 4];

__device__ __forceinline__ unsigned flipf(float v) {
    unsigned ub = __float_as_uint(v);
    return (ub & 0x80000000u) ? ~ub : (ub | 0x80000000u);
}

// ---------------------------------------------------------------------------
// Pass A: warp-per-tile argmax. No smem, no syncthreads. 8 f4 loads / lane.
// grid (32, B) x 256 thr: warp w of block handles tile blockIdx.x*8 + w.
// ---------------------------------------------------------------------------
__global__ __launch_bounds__(256)
void k_tilemax(const float* __restrict__ umap) {
    const int b = blockIdx.y;
    const int lane = threadIdx.x & 31;
    const int tile = blockIdx.x * 8 + (threadIdx.x >> 5);
    const int tx1 = (tile & (TPD - 1)) * TILE;
    const int ty1 = (tile >> 4) * TILE;
    const float* __restrict__ um = umap + ((size_t)b << 18);

    float4 f[8];
#pragma unroll
    for (int q = 0; q < 8; q++) {
        const int f4 = q * 32 + lane;
        const int y = ty1 + (f4 >> 3);
        const int x = tx1 + ((f4 & 7) << 2);
        f[q] = *(const float4*)(um + (y << 9) + x);
    }

    float m = -1.0f; int idx = 0;
#pragma unroll
    for (int q = 0; q < 8; q++) {
        const int f4 = q * 32 + lane;
        const int gi = ((ty1 + (f4 >> 3)) << 9) + tx1 + ((f4 & 7) << 2);
        if (f[q].x > m) { m = f[q].x; idx = gi; }
        if (f[q].y > m) { m = f[q].y; idx = gi + 1; }
        if (f[q].z > m) { m = f[q].z; idx = gi + 2; }
        if (f[q].w > m) { m = f[q].w; idx = gi + 3; }
    }

    unsigned long long best =
        ((unsigned long long)flipf(m) << 32) | (unsigned)~(unsigned)idx;
#pragma unroll
    for (int off = 16; off > 0; off >>= 1) {
        unsigned long long o = __shfl_down_sync(0xFFFFFFFFu, best, off);
        best = (o > best) ? o : best;
    }
    if (lane == 0) g_tiles[b * NTILE + tile] = best;
}

// ---------------------------------------------------------------------------
// Pass B: fused 4-round greedy selection. One block (512 thr) per batch.
// Rescan uses interval bitmasks instead of per-element box tests.
// ---------------------------------------------------------------------------
__global__ __launch_bounds__(512)
void k_select(const float* __restrict__ umap, float* __restrict__ out_coords) {
    const int b = blockIdx.x;
    const int t = threadIdx.x;
    const int lane = t & 31, wid = t >> 5;
    const float* __restrict__ um = umap + ((size_t)b << 18);

    __shared__ unsigned long long stile[NTILE];
    __shared__ unsigned long long sred[16];
    __shared__ int sbox[NPATCH][4];     // fixed boxes
    __shared__ int sebox[NPATCH][4];    // expanded (±MARGIN)
    __shared__ int slist[64];
    __shared__ int scount;

    if (t < NTILE) stile[t] = g_tiles[b * NTILE + t];

    for (int k = 0; k < NPATCH; k++) {
        __syncthreads();
        // block-wide max over 256 tile entries
        unsigned long long v = (t < NTILE) ? stile[t] : 0ULL;
#pragma unroll
        for (int off = 16; off > 0; off >>= 1) {
            unsigned long long o = __shfl_down_sync(0xFFFFFFFFu, v, off);
            v = (o > v) ? o : v;
        }
        if (lane == 0) sred[wid] = v;
        __syncthreads();
        if (t == 0) {
            unsigned long long w = sred[0];
#pragma unroll
            for (int j = 1; j < 8; j++) w = (sred[j] > w) ? sred[j] : w;
            const int idx = (int)(~(unsigned)(w & 0xFFFFFFFFu));
            const int yc = idx >> 9, xc = idx & (HW - 1);

            int x1 = max(0, xc - HALF), x2 = min(HW, xc + HALF);
            if (x2 - x1 < P) { if (x1 == 0) x2 = P; else x1 = x2 - P; }
            int y1 = max(0, yc - HALF), y2 = min(HW, yc + HALF);
            if (y2 - y1 < P) { if (y1 == 0) y2 = P; else y1 = y2 - P; }

            sbox[k][0] = x1; sbox[k][1] = y1; sbox[k][2] = x2; sbox[k][3] = y2;
            sebox[k][0] = x1 - MARGIN; sebox[k][1] = y1 - MARGIN;
            sebox[k][2] = x2 + MARGIN; sebox[k][3] = y2 + MARGIN;

            int* bx = &g_boxes[(b * NPATCH + k) * 4];
            bx[0] = x1; bx[1] = y1; bx[2] = x2; bx[3] = y2;
            float* oc = out_coords + (b * NPATCH + k) * 4;
            oc[0] = (float)x1; oc[1] = (float)y1;
            oc[2] = (float)x2; oc[3] = (float)y2;
            scount = 0;
        }
        __syncthreads();
        if (k == NPATCH - 1) break;

        // classify tiles vs newly added expanded box
        if (t < NTILE) {
            const int ex1 = sebox[k][0], ey1 = sebox[k][1];
            const int ex2 = sebox[k][2], ey2 = sebox[k][3];
            const int tx1 = (t & (TPD - 1)) * TILE, ty1 = (t >> 4) * TILE;
            const int tx2 = tx1 + TILE, ty2 = ty1 + TILE;
            if ((tx1 < ex2) && (tx2 > ex1) && (ty1 < ey2) && (ty2 > ey1)) {
                if ((tx1 >= ex1) && (tx2 <= ex2) && (ty1 >= ey1) && (ty2 <= ey2))
                    stile[t] = 0ULL;
                else
                    slist[atomicAdd(&scount, 1)] = t;
            }
        }
        __syncthreads();

        // warp-per-tile rescan of boundary tiles with boxes 0..k
        const int cnt = scount;
        for (int li = wid; li < cnt; li += 16) {
            const int tile = slist[li];
            const int tx1 = (tile & (TPD - 1)) * TILE;
            const int ty1 = (tile >> 4) * TILE;

            float4 f[8];
#pragma unroll
            for (int q = 0; q < 8; q++) {
                const int f4 = q * 32 + lane;
                const int y = ty1 + (f4 >> 3);
                const int x = tx1 + ((f4 & 7) << 2);
                f[q] = *(const float4*)(um + (y << 9) + x);
            }

            float m = -1.0f; int idx = 0;
#pragma unroll
            for (int q = 0; q < 8; q++) {
                const int f4 = q * 32 + lane;
                const int y = ty1 + (f4 >> 3);
                const int x = tx1 + ((f4 & 7) << 2);
                // 4-bit suppression mask for px [x, x+4)
                unsigned mask = 0;
                for (int j = 0; j <= k; j++) {
                    if (y >= sebox[j][1] && y < sebox[j][3]) {
                        const int lo = max(sebox[j][0] - x, 0);
                        const int hi = min(sebox[j][2] - x, 4);
                        if (hi > lo) mask |= ((1u << (hi - lo)) - 1u) << lo;
                    }
                }
                const int gi = (y << 9) + x;
                const float vals[4] = {f[q].x, f[q].y, f[q].z, f[q].w};
#pragma unroll
                for (int e = 0; e < 4; e++)
                    if (!((mask >> e) & 1u) && vals[e] > m) { m = vals[e]; idx = gi + e; }
            }

            unsigned long long best =
                ((unsigned long long)flipf(m) << 32) | (unsigned)~(unsigned)idx;
#pragma unroll
            for (int off = 16; off > 0; off >>= 1) {
                unsigned long long o = __shfl_down_sync(0xFFFFFFFFu, best, off);
                best = (o > best) ? o : best;
            }
            if (lane == 0) stile[tile] = best;
        }
    }
}

// ---------------------------------------------------------------------------
// Pass C: extract. 512 thr/block, one block per (b,n,c); 8 fully unrolled
// iterations with all loads issued before stores (high MLP).
// ---------------------------------------------------------------------------
__global__ __launch_bounds__(512)
void k_extract(const float* __restrict__ images, float* __restrict__ out) {
    const int blk = blockIdx.x;
    const int c = blk % C;
    const int n = (blk / C) % NPATCH;
    const int b = blk / (C * NPATCH);

    const int x1 = g_boxes[(b * NPATCH + n) * 4 + 0];
    const int y1 = g_boxes[(b * NPATCH + n) * 4 + 1];

    const float* __restrict__ src =
        images + (((size_t)(b * C + c) * HW) + y1) * HW + x1;
    float4* __restrict__ dst =
        (float4*)(out + (size_t)((b * NPATCH + n) * C + c) * (P * P));

    float4 r[8];
#pragma unroll
    for (int it = 0; it < 8; it++) {
        const int v = it * 512 + threadIdx.x;
        const int i = v >> 5;
        const int j = (v & 31) * 4;
        const float* s = src + (size_t)i * HW + j;
        r[it] = make_float4(s[0], s[1], s[2], s[3]);
    }
#pragma unroll
    for (int it = 0; it < 8; it++)
        dst[it * 512 + threadIdx.x] = r[it];
}

// ---------------------------------------------------------------------------
extern "C" void kernel_launch(void* const* d_in, const int* in_sizes, int n_in,
                              void* d_out, int out_size) {
    const float* images = (const float*)d_in[0];   // [32,3,512,512]
    const float* umaps  = (const float*)d_in[1];   // [32,1,512,512]
    float* out = (float*)d_out;
    float* out_coords = out + PATCH_OUT_ELEMS;

    k_tilemax<<<dim3(32, B), 256>>>(umaps);
    k_select<<<B, 512>>>(umaps, out_coords);
    k_extract<<<B * NPATCH * C, 512>>>(images, out);
}

// round 5
// speedup vs baseline: 3.1887x; 1.1592x over previous
#include <cuda_runtime.h>
#include <cstdint>

#define B 32
#define HW 512
#define NPIX (HW * HW)
#define NPATCH 4
#define C 3
#define P 128
#define HALF 64
#define MARGIN 32
#define TILE 32
#define TPD (HW / TILE)          // 16
#define NTILE (TPD * TPD)        // 256
#define PATCH_OUT_ELEMS (B * NPATCH * C * P * P)

__device__ unsigned long long g_tiles[B * NTILE];
__device__ int g_boxes[B * NPATCH * 4];

__device__ __forceinline__ unsigned flipf(float v) {
    unsigned ub = __float_as_uint(v);
    return (ub & 0x80000000u) ? ~ub : (ub | 0x80000000u);
}

// ---------------------------------------------------------------------------
// Pass A: warp-per-tile argmax. 128-thr blocks (4 tiles) for load balance.
// fmaxf tree + equality/min-index recovery (short dep chains).
// ---------------------------------------------------------------------------
__global__ __launch_bounds__(128)
void k_tilemax(const float* __restrict__ umap) {
    const int b = blockIdx.y;
    const int lane = threadIdx.x & 31;
    const int tile = blockIdx.x * 4 + (threadIdx.x >> 5);
    const int tx1 = (tile & (TPD - 1)) * TILE;
    const int ty1 = (tile >> 4) * TILE;
    const float* __restrict__ um = umap + ((size_t)b << 18);

    float4 f[8];
#pragma unroll
    for (int q = 0; q < 8; q++) {
        const int f4 = q * 32 + lane;
        const int y = ty1 + (f4 >> 3);
        const int x = tx1 + ((f4 & 7) << 2);
        f[q] = *(const float4*)(um + (y << 9) + x);
    }

    // tree max over 32 values
    float c4[8];
#pragma unroll
    for (int q = 0; q < 8; q++)
        c4[q] = fmaxf(fmaxf(f[q].x, f[q].y), fmaxf(f[q].z, f[q].w));
    float m = fmaxf(fmaxf(fmaxf(c4[0], c4[1]), fmaxf(c4[2], c4[3])),
                    fmaxf(fmaxf(c4[4], c4[5]), fmaxf(c4[6], c4[7])));

    // first-occurrence (min global index) recovery
    int idx = 0x7FFFFFFF;
#pragma unroll
    for (int q = 0; q < 8; q++) {
        const int f4 = q * 32 + lane;
        const int gi = ((ty1 + (f4 >> 3)) << 9) + tx1 + ((f4 & 7) << 2);
        if (f[q].x == m) idx = min(idx, gi);
        if (f[q].y == m) idx = min(idx, gi + 1);
        if (f[q].z == m) idx = min(idx, gi + 2);
        if (f[q].w == m) idx = min(idx, gi + 3);
    }

    unsigned long long best =
        ((unsigned long long)flipf(m) << 32) | (unsigned)~(unsigned)idx;
#pragma unroll
    for (int off = 16; off > 0; off >>= 1) {
        unsigned long long o = __shfl_down_sync(0xFFFFFFFFu, best, off);
        best = (o > best) ? o : best;
    }
    if (lane == 0) g_tiles[b * NTILE + tile] = best;
}

// ---------------------------------------------------------------------------
// Pass B: fused 4-round greedy selection. One 1024-thr block per batch.
// 32 warps -> each boundary tile rescanned by its own warp in parallel.
// ---------------------------------------------------------------------------
__global__ __launch_bounds__(1024)
void k_select(const float* __restrict__ umap, float* __restrict__ out_coords) {
    const int b = blockIdx.x;
    const int t = threadIdx.x;
    const int lane = t & 31, wid = t >> 5;
    const float* __restrict__ um = umap + ((size_t)b << 18);

    __shared__ unsigned long long stile[NTILE];
    __shared__ unsigned long long sred[32];
    __shared__ int sebox[NPATCH][4];    // expanded (±MARGIN)
    __shared__ int slist[64];
    __shared__ int scount;

    if (t < NTILE) stile[t] = g_tiles[b * NTILE + t];

    for (int k = 0; k < NPATCH; k++) {
        __syncthreads();
        unsigned long long v = (t < NTILE) ? stile[t] : 0ULL;
#pragma unroll
        for (int off = 16; off > 0; off >>= 1) {
            unsigned long long o = __shfl_down_sync(0xFFFFFFFFu, v, off);
            v = (o > v) ? o : v;
        }
        if (lane == 0) sred[wid] = v;
        __syncthreads();
        if (t == 0) {
            unsigned long long w = sred[0];
#pragma unroll
            for (int j = 1; j < 8; j++) w = (sred[j] > w) ? sred[j] : w;
            const int idx = (int)(~(unsigned)(w & 0xFFFFFFFFu));
            const int yc = idx >> 9, xc = idx & (HW - 1);

            int x1 = max(0, xc - HALF), x2 = min(HW, xc + HALF);
            if (x2 - x1 < P) { if (x1 == 0) x2 = P; else x1 = x2 - P; }
            int y1 = max(0, yc - HALF), y2 = min(HW, yc + HALF);
            if (y2 - y1 < P) { if (y1 == 0) y2 = P; else y1 = y2 - P; }

            sebox[k][0] = x1 - MARGIN; sebox[k][1] = y1 - MARGIN;
            sebox[k][2] = x2 + MARGIN; sebox[k][3] = y2 + MARGIN;

            int* bx = &g_boxes[(b * NPATCH + k) * 4];
            bx[0] = x1; bx[1] = y1; bx[2] = x2; bx[3] = y2;
            float* oc = out_coords + (b * NPATCH + k) * 4;
            oc[0] = (float)x1; oc[1] = (float)y1;
            oc[2] = (float)x2; oc[3] = (float)y2;
            scount = 0;
        }
        __syncthreads();
        if (k == NPATCH - 1) break;

        // classify tiles vs newly added expanded box
        if (t < NTILE) {
            const int ex1 = sebox[k][0], ey1 = sebox[k][1];
            const int ex2 = sebox[k][2], ey2 = sebox[k][3];
            const int tx1 = (t & (TPD - 1)) * TILE, ty1 = (t >> 4) * TILE;
            const int tx2 = tx1 + TILE, ty2 = ty1 + TILE;
            if ((tx1 < ex2) && (tx2 > ex1) && (ty1 < ey2) && (ty2 > ey1)) {
                if ((tx1 >= ex1) && (tx2 <= ex2) && (ty1 >= ey1) && (ty2 <= ey2))
                    stile[t] = 0ULL;
                else
                    slist[atomicAdd(&scount, 1)] = t;
            }
        }
        __syncthreads();

        // warp-per-tile rescan of boundary tiles against boxes 0..k
        const int cnt = scount;
        for (int li = wid; li < cnt; li += 32) {
            const int tile = slist[li];
            const int tx1 = (tile & (TPD - 1)) * TILE;
            const int ty1 = (tile >> 4) * TILE;

            float4 f[8];
#pragma unroll
            for (int q = 0; q < 8; q++) {
                const int f4 = q * 32 + lane;
                const int y = ty1 + (f4 >> 3);
                const int x = tx1 + ((f4 & 7) << 2);
                f[q] = *(const float4*)(um + (y << 9) + x);
            }

            float m = -1.0f; int idx = 0;
#pragma unroll
            for (int q = 0; q < 8; q++) {
                const int f4 = q * 32 + lane;
                const int y = ty1 + (f4 >> 3);
                const int x = tx1 + ((f4 & 7) << 2);
                unsigned mask = 0;
                for (int j = 0; j <= k; j++) {
                    if (y >= sebox[j][1] && y < sebox[j][3]) {
                        const int lo = max(sebox[j][0] - x, 0);
                        const int hi = min(sebox[j][2] - x, 4);
                        if (hi > lo) mask |= ((1u << (hi - lo)) - 1u) << lo;
                    }
                }
                const int gi = (y << 9) + x;
                const float vals[4] = {f[q].x, f[q].y, f[q].z, f[q].w};
#pragma unroll
                for (int e = 0; e < 4; e++)
                    if (!((mask >> e) & 1u) && vals[e] > m) { m = vals[e]; idx = gi + e; }
            }

            unsigned long long best =
                ((unsigned long long)flipf(m) << 32) | (unsigned)~(unsigned)idx;
#pragma unroll
            for (int off = 16; off > 0; off >>= 1) {
                unsigned long long o = __shfl_down_sync(0xFFFFFFFFu, best, off);
                best = (o > best) ? o : best;
            }
            if (lane == 0) stile[tile] = best;
        }
    }
}

// ---------------------------------------------------------------------------
// Pass C: extract. Quarter-patch blocks: grid = B*N*C*4, 256 thr, 4 f4/thread.
// ---------------------------------------------------------------------------
__global__ __launch_bounds__(256)
void k_extract(const float* __restrict__ images, float* __restrict__ out) {
    const int blk = blockIdx.x;
    const int sub = blk & 3;                 // quarter (32 rows)
    const int pc = blk >> 2;
    const int c = pc % C;
    const int n = (pc / C) % NPATCH;
    const int b = pc / (C * NPATCH);

    const int x1 = g_boxes[(b * NPATCH + n) * 4 + 0];
    const int y1 = g_boxes[(b * NPATCH + n) * 4 + 1];

    const float* __restrict__ src =
        images + (((size_t)(b * C + c) * HW) + y1 + sub * 32) * HW + x1;
    float4* __restrict__ dst =
        (float4*)(out + (size_t)((b * NPATCH + n) * C + c) * (P * P)) + sub * 1024;

    float4 r[4];
#pragma unroll
    for (int it = 0; it < 4; it++) {
        const int v = it * 256 + threadIdx.x;     // 0..1023 f4 within quarter
        const int i = v >> 5;                      // row 0..31
        const int j = (v & 31) * 4;                // col
        const float* s = src + (size_t)i * HW + j;
        r[it] = make_float4(s[0], s[1], s[2], s[3]);
    }
#pragma unroll
    for (int it = 0; it < 4; it++)
        dst[it * 256 + threadIdx.x] = r[it];
}

// ---------------------------------------------------------------------------
extern "C" void kernel_launch(void* const* d_in, const int* in_sizes, int n_in,
                              void* d_out, int out_size) {
    const float* images = (const float*)d_in[0];   // [32,3,512,512]
    const float* umaps  = (const float*)d_in[1];   // [32,1,512,512]
    float* out = (float*)d_out;
    float* out_coords = out + PATCH_OUT_ELEMS;

    k_tilemax<<<dim3(64, B), 128>>>(umaps);
    k_select<<<B, 1024>>>(umaps, out_coords);
    k_extract<<<B * NPATCH * C * 4, 256>>>(images, out);
}